// round 5
// baseline (speedup 1.0000x reference)
#include <cuda_runtime.h>

// UnarySqrt recurrence, unipolar, jk_trace=True.
// On exact {0.0f, 1.0f} IEEE patterns (0x00000000 / 0x3F800000):
//   out    = trace | x     ( == (1-trace)*x + trace )
//   trace' = x & ~trace    ( == out * (1-trace) )
// Bit-exact vs the float reference (rel_err=0.0 since R3).
//
// R5: software-pipelined chunks. 2 column streams/thread (i, i+half),
// CH=2 t-steps per chunk. Prefetch next chunk's 4 loads before computing and
// storing the current chunk: keeps ~8 loads in flight (R4's DRAM win) while
// spreading stores uniformly (kills R4's terminal writeback burst that
// penalized back-to-back graph replays).
// Geometry: 256 thr x 512 CTAs = 4 CTAs/SM, one balanced wave.

#define T_STEPS 64
#define CH 2

__device__ __forceinline__ void step2(uint4 x[CH], uint4& tr)
{
    #pragma unroll
    for (int k = 0; k < CH; ++k) {
        uint4 o;
        o.x = x[k].x | tr.x;   o.y = x[k].y | tr.y;
        o.z = x[k].z | tr.z;   o.w = x[k].w | tr.w;
        tr.x = x[k].x & ~tr.x; tr.y = x[k].y & ~tr.y;
        tr.z = x[k].z & ~tr.z; tr.w = x[k].w & ~tr.w;
        x[k] = o;              // x[k] now holds out
    }
}

__global__ __launch_bounds__(256)
void unary_sqrt_kernel(const uint4* __restrict__ bits,
                       const uint4* __restrict__ trace0,
                       uint4* __restrict__ out,
                       int nvec, int half)
{
    int i = blockIdx.x * blockDim.x + threadIdx.x;
    if (i >= half) return;
    int j = i + half;

    uint4 ta = __ldcs(&trace0[i]);
    uint4 tb = __ldcs(&trace0[j]);

    uint4 xa[CH], xb[CH];   // current chunk
    uint4 ya[CH], yb[CH];   // prefetched next chunk

    // prologue: load chunk 0
    #pragma unroll
    for (int k = 0; k < CH; ++k) {
        const size_t base = (size_t)k * nvec;
        xa[k] = __ldcs(&bits[base + i]);
        xb[k] = __ldcs(&bits[base + j]);
    }

    #pragma unroll
    for (int tbase = 0; tbase < T_STEPS; tbase += CH) {
        // prefetch next chunk (address-independent of current compute)
        if (tbase + CH < T_STEPS) {
            #pragma unroll
            for (int k = 0; k < CH; ++k) {
                const size_t base = (size_t)(tbase + CH + k) * nvec;
                ya[k] = __ldcs(&bits[base + i]);
                yb[k] = __ldcs(&bits[base + j]);
            }
        }

        // compute current chunk
        step2(xa, ta);
        step2(xb, tb);

        // store current chunk
        #pragma unroll
        for (int k = 0; k < CH; ++k) {
            const size_t base = (size_t)(tbase + k) * nvec;
            __stcs(&out[base + i], xa[k]);
            __stcs(&out[base + j], xb[k]);
        }

        // rotate
        #pragma unroll
        for (int k = 0; k < CH; ++k) {
            xa[k] = ya[k];
            xb[k] = yb[k];
        }
    }
}

extern "C" void kernel_launch(void* const* d_in, const int* in_sizes, int n_in,
                              void* d_out, int out_size)
{
    // metadata order: input [T, N] float32, trace0 [N] float32
    const uint4* bits   = (const uint4*)d_in[0];
    const uint4* trace0 = (const uint4*)d_in[1];
    uint4*       out    = (uint4*)d_out;

    int N    = in_sizes[1];   // 1048576
    int nvec = N / 4;         // 262144 uint4 vectors
    int half = nvec / 2;      // 131072

    int threads = 256;
    int blocks  = (half + threads - 1) / threads;  // 512 -> 4 CTAs/SM, 1 wave
    unary_sqrt_kernel<<<blocks, threads>>>(bits, trace0, out, nvec, half);
}

// round 6
// speedup vs baseline: 1.1172x; 1.1172x over previous
#include <cuda_runtime.h>

// UnarySqrt recurrence, unipolar, jk_trace=True.
// On exact {0.0f, 1.0f} IEEE patterns (0x00000000 / 0x3F800000):
//   out    = trace | x     ( == (1-trace)*x + trace )
//   trace' = x & ~trace    ( == out * (1-trace) )
// Bit-exact vs the float reference (rel_err=0.0 since R3).
//
// R6: R4's time-tiled burst structure (best in-kernel DRAM%: 8 back-to-back
// 16B loads -> compute -> 8 back-to-back 16B stores) but with DEFAULT cache
// policy. The harness times back-to-back graph replays; evict-first hints
// (__ldcs/__stcs) destroyed the L2 slice that survives between replays
// (126MB L2 vs 512MB working set), which is why every hinted round ran
// slower on the bench than on flushed-cache ncu. Let L2 keep what it can.
// Geometry: 256 thr x 512 CTAs = 4 CTAs/SM, one balanced wave.

#define T_STEPS 64
#define CH 4

__global__ __launch_bounds__(256)
void unary_sqrt_kernel(const uint4* __restrict__ bits,
                       const uint4* __restrict__ trace0,
                       uint4* __restrict__ out,
                       int nvec, int half)
{
    int i = blockIdx.x * blockDim.x + threadIdx.x;
    if (i >= half) return;
    int j = i + half;

    uint4 ta = trace0[i];
    uint4 tb = trace0[j];

    for (int tbase = 0; tbase < T_STEPS; tbase += CH) {
        uint4 xa[CH], xb[CH];

        // burst: 2*CH address-independent 16B loads (default policy)
        #pragma unroll
        for (int k = 0; k < CH; ++k) {
            const size_t base = (size_t)(tbase + k) * nvec;
            xa[k] = bits[base + i];
            xb[k] = bits[base + j];
        }

        // recurrence (in-place: x[k] becomes out[k])
        #pragma unroll
        for (int k = 0; k < CH; ++k) {
            uint4 oa, ob;
            oa.x = xa[k].x | ta.x;  oa.y = xa[k].y | ta.y;
            oa.z = xa[k].z | ta.z;  oa.w = xa[k].w | ta.w;
            ob.x = xb[k].x | tb.x;  ob.y = xb[k].y | tb.y;
            ob.z = xb[k].z | tb.z;  ob.w = xb[k].w | tb.w;

            ta.x = xa[k].x & ~ta.x;  ta.y = xa[k].y & ~ta.y;
            ta.z = xa[k].z & ~ta.z;  ta.w = xa[k].w & ~ta.w;
            tb.x = xb[k].x & ~tb.x;  tb.y = xb[k].y & ~tb.y;
            tb.z = xb[k].z & ~tb.z;  tb.w = xb[k].w & ~tb.w;

            xa[k] = oa;  xb[k] = ob;
        }

        // burst: 2*CH back-to-back 16B stores (default policy)
        #pragma unroll
        for (int k = 0; k < CH; ++k) {
            const size_t base = (size_t)(tbase + k) * nvec;
            out[base + i] = xa[k];
            out[base + j] = xb[k];
        }
    }
}

extern "C" void kernel_launch(void* const* d_in, const int* in_sizes, int n_in,
                              void* d_out, int out_size)
{
    // metadata order: input [T, N] float32, trace0 [N] float32
    const uint4* bits   = (const uint4*)d_in[0];
    const uint4* trace0 = (const uint4*)d_in[1];
    uint4*       out    = (uint4*)d_out;

    int N    = in_sizes[1];   // 1048576
    int nvec = N / 4;         // 262144 uint4 vectors
    int half = nvec / 2;      // 131072

    int threads = 256;
    int blocks  = (half + threads - 1) / threads;  // 512 -> 4 CTAs/SM, 1 wave
    unary_sqrt_kernel<<<blocks, threads>>>(bits, trace0, out, nvec, half);
}